// round 2
// baseline (speedup 1.0000x reference)
#include <cuda_runtime.h>

// CorrAttentionBias: out[b,h,i,j] = attn + alpha*edge + beta*cs_i*cs_j, masked to NEG.
// B=2, H=16, L=2048. Pure HBM-streaming; skip attn reads on fully-masked rows.
// Mask dtype (int32 vs uint8 bool) is auto-detected by a safe pre-pass.

#define ALPHA 0.5f
#define BETA  0.1f
#define NEGV  -100000.0f

namespace {
constexpr int B = 2;
constexpr int H = 16;
constexpr int L = 2048;
constexpr int THREADS = 256;
constexpr int V4_PER_THREAD = (L / 4) / THREADS;  // 2
}

// 0 = mask is int32 (one int per element), 1 = mask is uint8 (one byte per element)
__device__ int g_mask_is_u8;

// Pre-pass: inspect first 4096 BYTES of the mask buffer (in-bounds under both
// interpretations: int32 -> 16KB total, uint8 -> 4KB total). If mask is int32,
// the first 1024 words are elements 0..1023, all in {0,1}. If mask is uint8,
// words are 4 packed bool bytes -> some word > 1 with probability ~1.
__global__ void detect_mask_dtype(const int* __restrict__ mask_words)
{
    __shared__ int any_gt1;
    if (threadIdx.x == 0) any_gt1 = 0;
    __syncthreads();
    for (int k = threadIdx.x; k < 1024; k += blockDim.x) {
        unsigned w = (unsigned)mask_words[k];
        if (w > 1u) any_gt1 = 1;   // benign race: all writers write 1
    }
    __syncthreads();
    if (threadIdx.x == 0) g_mask_is_u8 = any_gt1;
}

__global__ __launch_bounds__(THREADS) void corr_bias_kernel(
    const float* __restrict__ attn,
    const float* __restrict__ c_local,
    const float* __restrict__ c_sink,
    const void* __restrict__ mask_raw,
    float* __restrict__ out)
{
    const int mask_is_u8 = g_mask_is_u8;
    const unsigned r = blockIdx.x;            // r = (b*H + h)*L + i
    const int i = r & (L - 1);
    const int b = r >> 15;                    // H*L = 32768
    const long long base = (long long)r * L;

    const int* __restrict__ m_i32 = (const int*)mask_raw;
    const unsigned char* __restrict__ m_u8 = (const unsigned char*)mask_raw;

    float4* __restrict__ o4 = reinterpret_cast<float4*>(out + base);

    const int row_masked = mask_is_u8 ? (int)m_u8[b * L + i] : m_i32[b * L + i];

    // Fully-masked row: write-only fast path (saves ~50% of attn reads).
    if (row_masked) {
        const float4 neg = make_float4(NEGV, NEGV, NEGV, NEGV);
        #pragma unroll
        for (int k = 0; k < V4_PER_THREAD; k++)
            o4[threadIdx.x + k * THREADS] = neg;
        return;
    }

    const float4* __restrict__ a4  = reinterpret_cast<const float4*>(attn + base);
    const float4* __restrict__ cs4 = reinterpret_cast<const float4*>(c_sink + b * L);
    const int4*   __restrict__ mi4 = reinterpret_cast<const int4*>(m_i32 + b * L);
    const uchar4* __restrict__ mu4 = reinterpret_cast<const uchar4*>(m_u8 + b * L);

    const float csi = BETA * c_sink[b * L + i];

    // Neighbor bias values, matching the reference's overwrite semantics:
    //   j = i+1 : alpha * c_local[b, i+1]                     (i <= L-2)
    //   j = i-1 : alpha * c_local[b, i-1]  if 2 <= i <= L-2
    //             alpha * c_local[b, i]    if i == 1 or i == L-1
    float nl = 0.f, nr = 0.f;
    if (i >= 1) {
        nl = (i >= 2 && i <= L - 2) ? ALPHA * c_local[b * L + i - 1]
                                    : ALPHA * c_local[b * L + i];
    }
    if (i <= L - 2) {
        nr = ALPHA * c_local[b * L + i + 1];
    }

    #pragma unroll
    for (int k = 0; k < V4_PER_THREAD; k++) {
        const int v = threadIdx.x + k * THREADS;  // float4 index within row
        const int j = v * 4;

        const float4 a  = a4[v];
        const float4 cs = cs4[v];

        int mj0, mj1, mj2, mj3;
        if (mask_is_u8) {
            const uchar4 m = mu4[v];
            mj0 = m.x; mj1 = m.y; mj2 = m.z; mj3 = m.w;
        } else {
            const int4 m = mi4[v];
            mj0 = m.x; mj1 = m.y; mj2 = m.z; mj3 = m.w;
        }

        float o0 = fmaf(csi, cs.x, a.x);
        float o1 = fmaf(csi, cs.y, a.y);
        float o2 = fmaf(csi, cs.z, a.z);
        float o3 = fmaf(csi, cs.w, a.w);

        // neighbor diagonals (at most one lane per vector hits)
        if (j - 3 <= i + 1 && i - 1 <= j + 3) {
            if (j + 0 == i - 1) o0 += nl; else if (j + 0 == i + 1) o0 += nr;
            if (j + 1 == i - 1) o1 += nl; else if (j + 1 == i + 1) o1 += nr;
            if (j + 2 == i - 1) o2 += nl; else if (j + 2 == i + 1) o2 += nr;
            if (j + 3 == i - 1) o3 += nl; else if (j + 3 == i + 1) o3 += nr;
        }

        if (mj0) o0 = NEGV;
        if (mj1) o1 = NEGV;
        if (mj2) o2 = NEGV;
        if (mj3) o3 = NEGV;

        o4[v] = make_float4(o0, o1, o2, o3);
    }
}

extern "C" void kernel_launch(void* const* d_in, const int* in_sizes, int n_in,
                              void* d_out, int out_size)
{
    const float* attn    = (const float*)d_in[0];
    const float* c_local = (const float*)d_in[1];
    const float* c_sink  = (const float*)d_in[2];
    const void*  mask    = d_in[3];
    float*       out     = (float*)d_out;

    detect_mask_dtype<<<1, 256>>>((const int*)mask);
    const int grid = B * H * L;  // 65536 row-blocks
    corr_bias_kernel<<<grid, THREADS>>>(attn, c_local, c_sink, mask, out);
}

// round 3
// speedup vs baseline: 1.0222x; 1.0222x over previous
#include <cuda_runtime.h>

// CorrAttentionBias: out[b,h,i,j] = attn + alpha*edge + beta*cs_i*cs_j, masked to NEG.
// B=2, H=16, L=2048. Pure HBM streaming; masked rows skip the attn read.
// Mask dtype (int32 vs uint8) detected inline per block from 16 broadcast words
// (P(wrong | u8) ~ 3e-15, deterministic for a fixed dataset) — no pre-kernel.

#define ALPHA 0.5f
#define BETA  0.1f
#define NEGV  -100000.0f

namespace {
constexpr int B = 2;
constexpr int H = 16;
constexpr int L = 2048;
constexpr int THREADS = 256;
constexpr int V4_PER_THREAD = (L / 4) / THREADS;  // 2
}

__global__ __launch_bounds__(THREADS) void corr_bias_kernel(
    const float* __restrict__ attn,
    const float* __restrict__ c_local,
    const float* __restrict__ c_sink,
    const void* __restrict__ mask_raw,
    float* __restrict__ out)
{
    // ---- inline mask-dtype detection: first 16 words of the buffer ----
    // int32 mask -> words are elements 0..15, all in {0,1}.
    // uint8 mask -> words pack 4 bool bytes; some word > 1 with P ~ 1-3e-15.
    const int4* __restrict__ mw = (const int4*)mask_raw;  // 64B, always in-bounds
    int any_gt1 = 0;
    #pragma unroll
    for (int q = 0; q < 4; q++) {
        const int4 w = __ldg(mw + q);                     // uniform broadcast, L1-hot
        any_gt1 |= ((unsigned)w.x > 1u) | ((unsigned)w.y > 1u) |
                   ((unsigned)w.z > 1u) | ((unsigned)w.w > 1u);
    }
    const int mask_is_u8 = any_gt1;                       // warp/block-uniform

    const unsigned r = blockIdx.x;            // r = (b*H + h)*L + i
    const int i = r & (L - 1);
    const int b = r >> 15;                    // H*L = 32768
    const long long base = (long long)r * L;

    const int* __restrict__ m_i32 = (const int*)mask_raw;
    const unsigned char* __restrict__ m_u8 = (const unsigned char*)mask_raw;

    float4* __restrict__ o4 = reinterpret_cast<float4*>(out + base);

    const int row_masked = mask_is_u8 ? (int)m_u8[b * L + i] : m_i32[b * L + i];

    // Fully-masked row: write-only fast path (saves ~50% of attn reads).
    if (row_masked) {
        const float4 neg = make_float4(NEGV, NEGV, NEGV, NEGV);
        #pragma unroll
        for (int k = 0; k < V4_PER_THREAD; k++)
            __stcs(&o4[threadIdx.x + k * THREADS], neg);
        return;
    }

    const float4* __restrict__ a4  = reinterpret_cast<const float4*>(attn + base);
    const float4* __restrict__ cs4 = reinterpret_cast<const float4*>(c_sink + b * L);
    const int4*   __restrict__ mi4 = reinterpret_cast<const int4*>(m_i32 + b * L);
    const uchar4* __restrict__ mu4 = reinterpret_cast<const uchar4*>(m_u8 + b * L);

    const float csi = BETA * c_sink[b * L + i];

    // Neighbor bias values, matching the reference's overwrite semantics:
    //   j = i+1 : alpha * c_local[b, i+1]                     (i <= L-2)
    //   j = i-1 : alpha * c_local[b, i-1]  if 2 <= i <= L-2
    //             alpha * c_local[b, i]    if i == 1 or i == L-1
    float nl = 0.f, nr = 0.f;
    if (i >= 1) {
        nl = (i >= 2 && i <= L - 2) ? ALPHA * c_local[b * L + i - 1]
                                    : ALPHA * c_local[b * L + i];
    }
    if (i <= L - 2) {
        nr = ALPHA * c_local[b * L + i + 1];
    }

    #pragma unroll
    for (int k = 0; k < V4_PER_THREAD; k++) {
        const int v = threadIdx.x + k * THREADS;  // float4 index within row
        const int j = v * 4;

        const float4 a  = __ldcs(&a4[v]);         // touch-once stream: evict-first
        const float4 cs = cs4[v];

        int mj0, mj1, mj2, mj3;
        if (mask_is_u8) {
            const uchar4 m = mu4[v];
            mj0 = m.x; mj1 = m.y; mj2 = m.z; mj3 = m.w;
        } else {
            const int4 m = mi4[v];
            mj0 = m.x; mj1 = m.y; mj2 = m.z; mj3 = m.w;
        }

        float o0 = fmaf(csi, cs.x, a.x);
        float o1 = fmaf(csi, cs.y, a.y);
        float o2 = fmaf(csi, cs.z, a.z);
        float o3 = fmaf(csi, cs.w, a.w);

        // neighbor diagonals (at most one lane per vector hits)
        if (j - 3 <= i + 1 && i - 1 <= j + 3) {
            if (j + 0 == i - 1) o0 += nl; else if (j + 0 == i + 1) o0 += nr;
            if (j + 1 == i - 1) o1 += nl; else if (j + 1 == i + 1) o1 += nr;
            if (j + 2 == i - 1) o2 += nl; else if (j + 2 == i + 1) o2 += nr;
            if (j + 3 == i - 1) o3 += nl; else if (j + 3 == i + 1) o3 += nr;
        }

        if (mj0) o0 = NEGV;
        if (mj1) o1 = NEGV;
        if (mj2) o2 = NEGV;
        if (mj3) o3 = NEGV;

        __stcs(&o4[v], make_float4(o0, o1, o2, o3));  // touch-once stream
    }
}

extern "C" void kernel_launch(void* const* d_in, const int* in_sizes, int n_in,
                              void* d_out, int out_size)
{
    const float* attn    = (const float*)d_in[0];
    const float* c_local = (const float*)d_in[1];
    const float* c_sink  = (const float*)d_in[2];
    const void*  mask    = d_in[3];
    float*       out     = (float*)d_out;

    const int grid = B * H * L;  // 65536 row-blocks
    corr_bias_kernel<<<grid, THREADS>>>(attn, c_local, c_sink, mask, out);
}

// round 4
// speedup vs baseline: 1.0310x; 1.0086x over previous
#include <cuda_runtime.h>

// CorrAttentionBias: out[b,h,i,j] = attn + alpha*edge + beta*cs_i*cs_j, masked to NEG.
// B=2, H=16, L=2048. Pure HBM streaming; masked rows skip the attn read.
// Mask dtype is int32 (proven: uint8 interpretation fails rel_err 0.91,
// int32 path passes at 5e-14 on this fixed dataset).

#define ALPHA 0.5f
#define BETA  0.1f
#define NEGV  -100000.0f

namespace {
constexpr int B = 2;
constexpr int H = 16;
constexpr int L = 2048;
constexpr int THREADS = 256;
constexpr int V4_PER_THREAD = (L / 4) / THREADS;  // 2
}

__global__ __launch_bounds__(THREADS) void corr_bias_kernel(
    const float* __restrict__ attn,
    const float* __restrict__ c_local,
    const float* __restrict__ c_sink,
    const int* __restrict__ mask,     // int32 per element
    float* __restrict__ out)
{
    const unsigned r = blockIdx.x;            // r = (b*H + h)*L + i
    const int i = r & (L - 1);
    const int b = r >> 15;                    // H*L = 32768
    const long long base = (long long)r * L;

    float4* __restrict__ o4 = reinterpret_cast<float4*>(out + base);

    // Fully-masked row: write-only fast path (saves ~50% of attn reads).
    if (mask[b * L + i]) {
        const float4 neg = make_float4(NEGV, NEGV, NEGV, NEGV);
        #pragma unroll
        for (int k = 0; k < V4_PER_THREAD; k++)
            o4[threadIdx.x + k * THREADS] = neg;
        return;
    }

    const float4* __restrict__ a4  = reinterpret_cast<const float4*>(attn + base);
    const float4* __restrict__ cs4 = reinterpret_cast<const float4*>(c_sink + b * L);
    const int4*   __restrict__ mi4 = reinterpret_cast<const int4*>(mask + b * L);

    const float csi = BETA * c_sink[b * L + i];

    // Neighbor bias values, matching the reference's overwrite semantics:
    //   j = i+1 : alpha * c_local[b, i+1]                     (i <= L-2)
    //   j = i-1 : alpha * c_local[b, i-1]  if 2 <= i <= L-2
    //             alpha * c_local[b, i]    if i == 1 or i == L-1
    float nl = 0.f, nr = 0.f;
    if (i >= 1) {
        nl = (i >= 2 && i <= L - 2) ? ALPHA * c_local[b * L + i - 1]
                                    : ALPHA * c_local[b * L + i];
    }
    if (i <= L - 2) {
        nr = ALPHA * c_local[b * L + i + 1];
    }

    #pragma unroll
    for (int k = 0; k < V4_PER_THREAD; k++) {
        const int v = threadIdx.x + k * THREADS;  // float4 index within row
        const int j = v * 4;

        const float4 a  = a4[v];
        const float4 cs = cs4[v];
        const int4   m  = mi4[v];

        float o0 = fmaf(csi, cs.x, a.x);
        float o1 = fmaf(csi, cs.y, a.y);
        float o2 = fmaf(csi, cs.z, a.z);
        float o3 = fmaf(csi, cs.w, a.w);

        // neighbor diagonals (at most one lane per vector hits)
        if (j - 3 <= i + 1 && i - 1 <= j + 3) {
            if (j + 0 == i - 1) o0 += nl; else if (j + 0 == i + 1) o0 += nr;
            if (j + 1 == i - 1) o1 += nl; else if (j + 1 == i + 1) o1 += nr;
            if (j + 2 == i - 1) o2 += nl; else if (j + 2 == i + 1) o2 += nr;
            if (j + 3 == i - 1) o3 += nl; else if (j + 3 == i + 1) o3 += nr;
        }

        if (m.x) o0 = NEGV;
        if (m.y) o1 = NEGV;
        if (m.z) o2 = NEGV;
        if (m.w) o3 = NEGV;

        o4[v] = make_float4(o0, o1, o2, o3);
    }
}

extern "C" void kernel_launch(void* const* d_in, const int* in_sizes, int n_in,
                              void* d_out, int out_size)
{
    const float* attn    = (const float*)d_in[0];
    const float* c_local = (const float*)d_in[1];
    const float* c_sink  = (const float*)d_in[2];
    const int*   mask    = (const int*)d_in[3];
    float*       out     = (float*)d_out;

    const int grid = B * H * L;  // 65536 row-blocks
    corr_bias_kernel<<<grid, THREADS>>>(attn, c_local, c_sink, mask, out);
}

// round 5
// speedup vs baseline: 1.0315x; 1.0005x over previous
#include <cuda_runtime.h>

// CorrAttentionBias: out[b,h,i,j] = attn + alpha*edge + beta*cs_i*cs_j, masked to NEG.
// B=2, H=16, L=2048. HBM streaming. Two consecutive rows (i, i+1) per block:
// they share the same c_sink/mask column vectors (one load serves both rows)
// and give 4 independent attn loads per thread for deeper MLP.
// Mask dtype is int32 (proven on this dataset: uint8 read fails, int32 passes 5e-14).

#define ALPHA 0.5f
#define BETA  0.1f
#define NEGV  -100000.0f

namespace {
constexpr int B = 2;
constexpr int H = 16;
constexpr int L = 2048;
constexpr int THREADS = 256;
constexpr int V4_PER_ROW = L / 4;                      // 512
constexpr int K_ITERS = V4_PER_ROW / THREADS;          // 2 float4 per thread per row
}

__device__ __forceinline__ float edge_left(const float* cl, int b, int i) {
    // j = i-1 diagonal value for row i (reference overwrite semantics):
    //   alpha * c_local[b, i-1]  if 2 <= i <= L-2
    //   alpha * c_local[b, i]    if i == 1 or i == L-1
    //   0                        if i == 0
    if (i < 1) return 0.f;
    return (i >= 2 && i <= L - 2) ? ALPHA * cl[b * L + i - 1]
                                  : ALPHA * cl[b * L + i];
}

__device__ __forceinline__ float edge_right(const float* cl, int b, int i) {
    // j = i+1 diagonal value for row i: alpha * c_local[b, i+1] when i <= L-2.
    return (i <= L - 2) ? ALPHA * cl[b * L + i + 1] : 0.f;
}

__global__ __launch_bounds__(THREADS) void corr_bias_kernel(
    const float* __restrict__ attn,
    const float* __restrict__ c_local,
    const float* __restrict__ c_sink,
    const int* __restrict__ mask,     // int32 per element
    float* __restrict__ out)
{
    const unsigned p = blockIdx.x;            // row pair index
    const unsigned row0 = p * 2;              // (b*H + h)*L + i0,  i0 even
    const int i0 = row0 & (L - 1);
    const int b  = row0 >> 15;                // H*L = 32768

    const long long base0 = (long long)row0 * L;
    float4* __restrict__ oA = reinterpret_cast<float4*>(out + base0);
    float4* __restrict__ oB = oA + V4_PER_ROW;

    const int mk0 = mask[b * L + i0];
    const int mk1 = mask[b * L + i0 + 1];

    if (mk0 & mk1) {   // both rows fully masked: write-only fast path
        const float4 neg = make_float4(NEGV, NEGV, NEGV, NEGV);
        #pragma unroll
        for (int k = 0; k < K_ITERS; k++) {
            const int v = threadIdx.x + k * THREADS;
            oA[v] = neg;
            oB[v] = neg;
        }
        return;
    }

    const float4* __restrict__ aA  = reinterpret_cast<const float4*>(attn + base0);
    const float4* __restrict__ aB  = aA + V4_PER_ROW;
    const float4* __restrict__ cs4 = reinterpret_cast<const float4*>(c_sink + b * L);
    const int4*   __restrict__ mi4 = reinterpret_cast<const int4*>(mask + b * L);

    const float csi0 = BETA * c_sink[b * L + i0];
    const float csi1 = BETA * c_sink[b * L + i0 + 1];

    const float nl0 = edge_left (c_local, b, i0);
    const float nr0 = edge_right(c_local, b, i0);
    const float nl1 = edge_left (c_local, b, i0 + 1);
    const float nr1 = edge_right(c_local, b, i0 + 1);

    #pragma unroll
    for (int k = 0; k < K_ITERS; k++) {
        const int v = threadIdx.x + k * THREADS;  // float4 index within row
        const int j = v * 4;

        // Front-batched independent loads (shared column vectors load once).
        const float4 cs = cs4[v];
        const int4   m  = mi4[v];
        float4 a0, a1;
        if (!mk0) a0 = aA[v];
        if (!mk1) a1 = aB[v];

        const float s0 = csi0 * cs.x, s1 = csi0 * cs.y,
                    s2 = csi0 * cs.z, s3 = csi0 * cs.w;

        // ---- row i0 ----
        {
            float o0, o1, o2, o3;
            if (!mk0) {
                o0 = a0.x + s0; o1 = a0.y + s1; o2 = a0.z + s2; o3 = a0.w + s3;
                // neighbor diagonals for i0 (at most one lane hits)
                if (j + 0 == i0 - 1) o0 += nl0; else if (j + 0 == i0 + 1) o0 += nr0;
                if (j + 1 == i0 - 1) o1 += nl0; else if (j + 1 == i0 + 1) o1 += nr0;
                if (j + 2 == i0 - 1) o2 += nl0; else if (j + 2 == i0 + 1) o2 += nr0;
                if (j + 3 == i0 - 1) o3 += nl0; else if (j + 3 == i0 + 1) o3 += nr0;
                if (m.x) o0 = NEGV;
                if (m.y) o1 = NEGV;
                if (m.z) o2 = NEGV;
                if (m.w) o3 = NEGV;
            } else {
                o0 = o1 = o2 = o3 = NEGV;
            }
            oA[v] = make_float4(o0, o1, o2, o3);
        }

        // ---- row i0 + 1 ----
        {
            float o0, o1, o2, o3;
            if (!mk1) {
                o0 = fmaf(csi1, cs.x, a1.x);
                o1 = fmaf(csi1, cs.y, a1.y);
                o2 = fmaf(csi1, cs.z, a1.z);
                o3 = fmaf(csi1, cs.w, a1.w);
                const int i1 = i0 + 1;
                if (j + 0 == i1 - 1) o0 += nl1; else if (j + 0 == i1 + 1) o0 += nr1;
                if (j + 1 == i1 - 1) o1 += nl1; else if (j + 1 == i1 + 1) o1 += nr1;
                if (j + 2 == i1 - 1) o2 += nl1; else if (j + 2 == i1 + 1) o2 += nr1;
                if (j + 3 == i1 - 1) o3 += nl1; else if (j + 3 == i1 + 1) o3 += nr1;
                if (m.x) o0 = NEGV;
                if (m.y) o1 = NEGV;
                if (m.z) o2 = NEGV;
                if (m.w) o3 = NEGV;
            } else {
                o0 = o1 = o2 = o3 = NEGV;
            }
            oB[v] = make_float4(o0, o1, o2, o3);
        }
    }
}

extern "C" void kernel_launch(void* const* d_in, const int* in_sizes, int n_in,
                              void* d_out, int out_size)
{
    const float* attn    = (const float*)d_in[0];
    const float* c_local = (const float*)d_in[1];
    const float* c_sink  = (const float*)d_in[2];
    const int*   mask    = (const int*)d_in[3];
    float*       out     = (float*)d_out;

    const int grid = B * H * L / 2;  // 32768 row-pair blocks
    corr_bias_kernel<<<grid, THREADS>>>(attn, c_local, c_sink, mask, out);
}